// round 11
// baseline (speedup 1.0000x reference)
#include <cuda_runtime.h>
#include <cuda_bf16.h>
#include <math.h>

// Problem constants (RotatEDecoder_30674656428511)
#define D       128
#define MAX_N   100000
#define R_PAD   512          // padded type count (actual R <= 500)
#define FULL    0xffffffffu
#define E_MAX   1048576      // scratch capacity (problem E = 640000)
#define NB_MAX  256
#define CHUNK   4096

// Scratch (allocation-free rule: static __device__ globals)
__device__ float g_inv[MAX_N];            // 1/max(||z_i||, eps)
__device__ float g_cosp[R_PAD * D];       // cos(phase_rel), padded
__device__ int   g_is64;                  // index dtype flag
__device__ int4  g_rec[E_MAX];            // sorted records {src, dst, orig, type}
__device__ int   g_bhist[NB_MAX * R_PAD]; // per-block type histograms
__device__ int   g_boff[NB_MAX * R_PAD];  // per-block per-type scatter bases

__device__ __forceinline__ int idx_at(const void* p, size_t i, int is64) {
    return is64 ? (int)__ldg(&((const long long*)p)[i])
                : __ldg(&((const int*)p)[i]);
}

// ---------------------------------------------------------------------------
// Pre-pass: dtype detect (ballot), cos table, inverse norms.
// ---------------------------------------------------------------------------
__global__ __launch_bounds__(256)
void pre_kernel(const float* __restrict__ z, int N,
                const float* __restrict__ phase, int RD,
                const unsigned int* __restrict__ ei_words, int E) {
    if (blockIdx.x == 0 && threadIdx.x < 32) {
        int lane = threadIdx.x;
        unsigned int hi = (lane < E) ? ei_words[2 * lane + 1] : 0u;
        unsigned int any = __ballot_sync(FULL, hi != 0u);
        if (lane == 0) g_is64 = (any == 0u) ? 1 : 0;
    }
    int tid = blockIdx.x * blockDim.x + threadIdx.x;
    int nth = gridDim.x * blockDim.x;
    for (int i = tid; i < RD; i += nth)
        g_cosp[i] = cosf(phase[i]);

    int node = blockIdx.x * (blockDim.x >> 5) + (threadIdx.x >> 5);
    int lane = threadIdx.x & 31;
    if (node < N) {
        float4 v = reinterpret_cast<const float4*>(z + (size_t)node * D)[lane];
        float ss = v.x * v.x + v.y * v.y + v.z * v.z + v.w * v.w;
        #pragma unroll
        for (int o = 16; o; o >>= 1)
            ss += __shfl_xor_sync(FULL, ss, o);
        if (lane == 0)
            g_inv[node] = 1.0f / fmaxf(sqrtf(ss), 1e-12f);
    }
}

// ---------------------------------------------------------------------------
// Counting sort by edge type: per-block histogram -> scan -> scatter.
// ---------------------------------------------------------------------------
__global__ __launch_bounds__(256)
void hist_kernel(const void* __restrict__ et, int E) {
    __shared__ int h[R_PAD];
    for (int i = threadIdx.x; i < R_PAD; i += blockDim.x) h[i] = 0;
    __syncthreads();
    int is64 = g_is64;
    int lo = blockIdx.x * CHUNK, hi = min(E, lo + CHUNK);
    for (int e = lo + threadIdx.x; e < hi; e += blockDim.x)
        atomicAdd(&h[idx_at(et, e, is64)], 1);
    __syncthreads();
    for (int i = threadIdx.x; i < R_PAD; i += blockDim.x)
        g_bhist[blockIdx.x * R_PAD + i] = h[i];
}

__global__ void scan_kernel(int NB) {
    __shared__ int sm[R_PAD];
    int t = threadIdx.x;                    // one thread per type
    int run = 0;
    for (int b = 0; b < NB; b++) {          // within-type prefix over blocks
        int v = g_bhist[b * R_PAD + t];
        g_boff[b * R_PAD + t] = run;
        run += v;
    }
    sm[t] = run;
    __syncthreads();
    for (int off = 1; off < R_PAD; off <<= 1) {   // inclusive scan over types
        int v = (t >= off) ? sm[t - off] : 0;
        __syncthreads();
        sm[t] += v;
        __syncthreads();
    }
    int excl = sm[t] - run;                 // exclusive type base
    for (int b = 0; b < NB; b++)
        g_boff[b * R_PAD + t] += excl;
}

__global__ __launch_bounds__(256)
void scatter_kernel(const void* __restrict__ ei, const void* __restrict__ et, int E) {
    __shared__ int cur[R_PAD];
    for (int i = threadIdx.x; i < R_PAD; i += blockDim.x)
        cur[i] = g_boff[blockIdx.x * R_PAD + i];
    __syncthreads();
    int is64 = g_is64;
    int lo = blockIdx.x * CHUNK, hi = min(E, lo + CHUNK);
    for (int e = lo + threadIdx.x; e < hi; e += blockDim.x) {
        int t = idx_at(et, e, is64);
        int s = idx_at(ei, (size_t)e, is64);
        int d = idx_at(ei, (size_t)E + e, is64);
        int p = atomicAdd(&cur[t], 1);
        g_rec[p] = make_int4(s, d, e, t);
    }
}

// ---------------------------------------------------------------------------
// Sorted edge kernel: warp per 16 same-type (almost always) records.
// cos row loaded into registers ONCE per warp -> lines/edge 12.5 -> ~9.5.
// ---------------------------------------------------------------------------
__global__ __launch_bounds__(256)
void edge2_kernel(const float* __restrict__ z, float* __restrict__ out, int E) {
    int warp = blockIdx.x * (blockDim.x >> 5) + (threadIdx.x >> 5);
    int lane = threadIdx.x & 31;
    int base = warp * 16;
    if (base >= E) return;

    int idx = base + (lane & 15);
    if (idx >= E) idx = E - 1;
    int4 r = __ldg(&g_rec[idx]);            // coalesced: 16 recs x 16B = 2 lines

    int t0 = __shfl_sync(FULL, r.w, 0);
    bool uniform = __all_sync(FULL, r.w == t0);

    // inv products: lanes 0-15 hold inv[src_j], lanes 16-31 inv[dst_j]
    float iv  = __ldg(&g_inv[(lane < 16) ? r.x : r.y]);
    float ivp = iv * __shfl_down_sync(FULL, iv, 16);   // valid lanes 0..15

    // cos row in registers (shared by all 16 edges when uniform)
    float4 c = __ldg(&((const float4*)(g_cosp + t0 * D))[lane]);

    #pragma unroll
    for (int p = 0; p < 8; p++) {
        int j0 = 2 * p, j1 = 2 * p + 1;
        int s0 = __shfl_sync(FULL, r.x, j0);
        int d0 = __shfl_sync(FULL, r.y, j0);
        int s1 = __shfl_sync(FULL, r.x, j1);
        int d1 = __shfl_sync(FULL, r.y, j1);

        float4 a0 = __ldg(&((const float4*)(z + (size_t)s0 * D))[lane]);
        float4 b0 = __ldg(&((const float4*)(z + (size_t)d0 * D))[lane]);
        float4 a1 = __ldg(&((const float4*)(z + (size_t)s1 * D))[lane]);
        float4 b1 = __ldg(&((const float4*)(z + (size_t)d1 * D))[lane]);

        float4 c0 = c, c1 = c;
        if (!uniform) {                      // rare: warp straddles a bucket
            int tt0 = __shfl_sync(FULL, r.w, j0);
            int tt1 = __shfl_sync(FULL, r.w, j1);
            c0 = __ldg(&((const float4*)(g_cosp + tt0 * D))[lane]);
            c1 = __ldg(&((const float4*)(g_cosp + tt1 * D))[lane]);
        }

        float r0 = a0.x*c0.x*b0.x + a0.y*c0.y*b0.y + a0.z*c0.z*b0.z + a0.w*c0.w*b0.w;
        float r1 = a1.x*c1.x*b1.x + a1.y*c1.y*b1.y + a1.z*c1.z*b1.z + a1.w*c1.w*b1.w;

        // half-warp split reduction: 7 shfls for the pair
        float aa = r0 + __shfl_xor_sync(FULL, r0, 16);
        float bb = r1 + __shfl_xor_sync(FULL, r1, 16);
        float v = (lane < 16) ? aa : bb;
        #pragma unroll
        for (int o = 8; o; o >>= 1)
            v += __shfl_xor_sync(FULL, v, o);

        float invp = __shfl_sync(FULL, ivp, (lane < 16) ? j0 : j1);
        float scaled = v * invp;             // edge j0 on lane 0, j1 on lane 16
        float shi = __shfl_sync(FULL, scaled, 16);
        int o0 = __shfl_sync(FULL, r.z, j0);
        int o1 = __shfl_sync(FULL, r.z, j1);
        if (lane == 0) {
            if (base + j0 < E) out[o0] = scaled;
            if (base + j1 < E) out[o1] = shi;
        }
    }
}

// ---------------------------------------------------------------------------
// Fallback (unsorted, R7-style) for out-of-range sizes.
// ---------------------------------------------------------------------------
__global__ __launch_bounds__(256)
void edge_fallback(const float* __restrict__ z, const void* __restrict__ ei,
                   const void* __restrict__ et, float* __restrict__ out, int E) {
    int e = blockIdx.x * (blockDim.x >> 5) + (threadIdx.x >> 5);
    int lane = threadIdx.x & 31;
    if (e >= E) return;
    int is64 = g_is64;
    int s = idx_at(ei, (size_t)e, is64);
    int d = idx_at(ei, (size_t)E + e, is64);
    int t = idx_at(et, (size_t)e, is64);
    float4 a = __ldg(&((const float4*)(z + (size_t)s * D))[lane]);
    float4 b = __ldg(&((const float4*)(z + (size_t)d * D))[lane]);
    float4 c = __ldg(&((const float4*)(g_cosp + t * D))[lane]);
    float r = a.x*c.x*b.x + a.y*c.y*b.y + a.z*c.z*b.z + a.w*c.w*b.w;
    #pragma unroll
    for (int o = 16; o; o >>= 1)
        r += __shfl_xor_sync(FULL, r, o);
    if (lane == 0)
        out[e] = r * __ldg(&g_inv[s]) * __ldg(&g_inv[d]);
}

// ---------------------------------------------------------------------------
// Launch. Inputs: z[f32 N*D], edge_index[2*E i32/i64], edge_type[E], phase_rel.
// ---------------------------------------------------------------------------
extern "C" void kernel_launch(void* const* d_in, const int* in_sizes, int n_in,
                              void* d_out, int out_size) {
    const float* z  = (const float*)d_in[0];
    const void*  ei = d_in[1];
    const void*  et = d_in[2];
    const float* ph = (const float*)d_in[3];
    float* out = (float*)d_out;

    int N  = in_sizes[0] / D;
    int E  = in_sizes[2];
    int RD = in_sizes[3];
    if (E <= 0) return;

    pre_kernel<<<(N + 7) / 8, 256>>>(z, N, ph, RD, (const unsigned int*)ei, E);

    int NB = (E + CHUNK - 1) / CHUNK;
    if (E <= E_MAX && NB <= NB_MAX) {
        hist_kernel<<<NB, 256>>>(et, E);
        scan_kernel<<<1, R_PAD>>>(NB);
        scatter_kernel<<<NB, 256>>>(ei, et, E);
        int warps = (E + 15) / 16;
        edge2_kernel<<<(warps + 7) / 8, 256>>>(z, out, E);
    } else {
        edge_fallback<<<(E + 7) / 8, 256>>>(z, ei, et, out, E);
    }
}

// round 13
// speedup vs baseline: 1.0009x; 1.0009x over previous
#include <cuda_runtime.h>
#include <cuda_bf16.h>
#include <math.h>

// Problem constants (RotatEDecoder_30674656428511)
#define D       128
#define MAX_N   100000
#define R_PAD   512          // padded type count (actual R = 500)
#define FULL    0xffffffffu
#define CH      2048         // edges per block chunk
#define TPB     256

// Scratch (allocation-free rule: static __device__ globals)
__device__ float g_inv[MAX_N];        // 1/max(||z_i||, eps)
__device__ float g_cosp[R_PAD * D];   // cos(phase_rel)
__device__ int   g_is64;              // index dtype flag

__device__ __forceinline__ int idx_at(const void* p, size_t i, int is64) {
    return is64 ? (int)__ldg(&((const long long*)p)[i])
                : __ldg(&((const int*)p)[i]);
}

// ---------------------------------------------------------------------------
// Pre-pass: dtype detect (ballot), cos table, inverse norms. One launch.
// ---------------------------------------------------------------------------
__global__ __launch_bounds__(256)
void pre_kernel(const float* __restrict__ z, int N,
                const float* __restrict__ phase, int RD,
                const unsigned int* __restrict__ ei_words, int E) {
    if (blockIdx.x == 0 && threadIdx.x < 32) {
        int lane = threadIdx.x;
        unsigned int hi = (lane < E) ? ei_words[2 * lane + 1] : 0u;
        unsigned int any = __ballot_sync(FULL, hi != 0u);
        if (lane == 0) g_is64 = (any == 0u) ? 1 : 0;
    }
    int RDc = min(RD, R_PAD * D);
    int tid = blockIdx.x * blockDim.x + threadIdx.x;
    int nth = gridDim.x * blockDim.x;
    for (int i = tid; i < RDc; i += nth)
        g_cosp[i] = cosf(phase[i]);

    int node = blockIdx.x * (blockDim.x >> 5) + (threadIdx.x >> 5);
    int lane = threadIdx.x & 31;
    if (node < N) {
        float4 v = reinterpret_cast<const float4*>(z + (size_t)node * D)[lane];
        float ss = v.x * v.x + v.y * v.y + v.z * v.z + v.w * v.w;
        #pragma unroll
        for (int o = 16; o; o >>= 1)
            ss += __shfl_xor_sync(FULL, ss, o);
        if (lane == 0)
            g_inv[node] = 1.0f / fmaxf(sqrtf(ss), 1e-12f);
    }
}

// ---------------------------------------------------------------------------
// Block-local sorted edge kernel. Each block: stage 2048 edges in smem,
// counting-sort by type in smem (no global passes), then warps process 16
// sorted edges each, reloading the cos row only on type change (~4.8 loads
// per 16 edges instead of 16). out[orig] per edge -> deterministic.
// ---------------------------------------------------------------------------
__global__ __launch_bounds__(TPB)
void sedge_kernel(const float* __restrict__ z,
                  const void* __restrict__ ei,
                  const void* __restrict__ et,
                  float* __restrict__ out, int E) {
    __shared__ int2 s_sd[CH];                  // 16 KB
    __shared__ unsigned short s_type[CH];      // 4 KB
    __shared__ unsigned short s_perm[CH];      // 4 KB
    __shared__ int s_cnt[R_PAD];               // 2 KB

    int tid = threadIdx.x;
    int base = blockIdx.x * CH;
    int M = min(E - base, CH);
    int is64 = g_is64;

    for (int i = tid; i < R_PAD; i += TPB) s_cnt[i] = 0;
    __syncthreads();

    // Stage (coalesced) + histogram
    for (int i = tid; i < M; i += TPB) {
        int e = base + i;
        int s = idx_at(ei, (size_t)e, is64);
        int d = idx_at(ei, (size_t)E + e, is64);
        int t = idx_at(et, (size_t)e, is64);
        s_sd[i] = make_int2(s, d);
        s_type[i] = (unsigned short)t;
        atomicAdd(&s_cnt[t], 1);
    }
    __syncthreads();

    // Exclusive scan of 512 bins by warp 0 (16 bins per lane + warp scan)
    if (tid < 32) {
        int lane = tid;
        int vals[16], sum = 0;
        #pragma unroll
        for (int k = 0; k < 16; k++) { vals[k] = s_cnt[lane * 16 + k]; sum += vals[k]; }
        int x = sum;
        #pragma unroll
        for (int o = 1; o < 32; o <<= 1) {
            int y = __shfl_up_sync(FULL, x, o);
            if (lane >= o) x += y;
        }
        int excl = x - sum;
        #pragma unroll
        for (int k = 0; k < 16; k++) { int v = vals[k]; s_cnt[lane * 16 + k] = excl; excl += v; }
    }
    __syncthreads();

    // Scatter permutation (order within a type is arbitrary; values identical)
    for (int i = tid; i < M; i += TPB) {
        int pos = atomicAdd(&s_cnt[s_type[i]], 1);
        s_perm[pos] = (unsigned short)i;
    }
    __syncthreads();

    // Process 16 sorted edges per warp-group
    int warp = tid >> 5, lane = tid & 31;
    int ngroups = (M + 15) >> 4;
    for (int g = warp; g < ngroups; g += (TPB >> 5)) {
        int p = g * 16 + (lane & 15);
        int pc = min(p, M - 1);
        int lid = s_perm[pc];
        int2 sd = s_sd[lid];
        int tt = s_type[lid];
        int orig = base + lid;

        // inv product: lane j (0-15) ends with inv[src_j]*inv[dst_j]
        float iv = __ldg(&g_inv[(lane < 16) ? sd.x : sd.y]);
        float ivp = iv * __shfl_down_sync(FULL, iv, 16);

        int t_cur = __shfl_sync(FULL, tt, 0);
        float4 c = __ldg(&((const float4*)(g_cosp + t_cur * D))[lane]);

        #pragma unroll
        for (int pr = 0; pr < 8; pr++) {
            int j0 = 2 * pr, j1 = 2 * pr + 1;
            int s0 = __shfl_sync(FULL, sd.x, j0);
            int d0 = __shfl_sync(FULL, sd.y, j0);
            int s1 = __shfl_sync(FULL, sd.x, j1);
            int d1 = __shfl_sync(FULL, sd.y, j1);
            int tA = __shfl_sync(FULL, tt, j0);   // uniform across warp
            int tB = __shfl_sync(FULL, tt, j1);

            float4 a0 = __ldg(&((const float4*)(z + (size_t)s0 * D))[lane]);
            float4 b0 = __ldg(&((const float4*)(z + (size_t)d0 * D))[lane]);
            float4 a1 = __ldg(&((const float4*)(z + (size_t)s1 * D))[lane]);
            float4 b1 = __ldg(&((const float4*)(z + (size_t)d1 * D))[lane]);

            if (tA != t_cur) { c = __ldg(&((const float4*)(g_cosp + tA * D))[lane]); t_cur = tA; }
            float4 c0 = c;
            if (tB != t_cur) { c = __ldg(&((const float4*)(g_cosp + tB * D))[lane]); t_cur = tB; }
            float4 c1 = c;

            float r0 = a0.x*c0.x*b0.x + a0.y*c0.y*b0.y + a0.z*c0.z*b0.z + a0.w*c0.w*b0.w;
            float r1 = a1.x*c1.x*b1.x + a1.y*c1.y*b1.y + a1.z*c1.z*b1.z + a1.w*c1.w*b1.w;

            // half-warp split reduction: 7 shfls for the pair
            float aa = r0 + __shfl_xor_sync(FULL, r0, 16);
            float bb = r1 + __shfl_xor_sync(FULL, r1, 16);
            float v = (lane < 16) ? aa : bb;
            #pragma unroll
            for (int o = 8; o; o >>= 1)
                v += __shfl_xor_sync(FULL, v, o);

            float invp = __shfl_sync(FULL, ivp, (lane < 16) ? j0 : j1);
            float scaled = v * invp;             // edge j0 on lane 0, j1 on lane 16
            float shi = __shfl_sync(FULL, scaled, 16);
            int o0 = __shfl_sync(FULL, orig, j0);
            int o1 = __shfl_sync(FULL, orig, j1);
            if (lane == 0) {
                if (g * 16 + j0 < M) out[o0] = scaled;
                if (g * 16 + j1 < M) out[o1] = shi;
            }
        }
    }
}

// ---------------------------------------------------------------------------
// Fallback for R > R_PAD (never hit at problem sizes): cos computed inline.
// ---------------------------------------------------------------------------
__global__ __launch_bounds__(256)
void edge_fallback(const float* __restrict__ z, const void* __restrict__ ei,
                   const void* __restrict__ et, const float* __restrict__ phase,
                   float* __restrict__ out, int E) {
    int e = blockIdx.x * (blockDim.x >> 5) + (threadIdx.x >> 5);
    int lane = threadIdx.x & 31;
    if (e >= E) return;
    int is64 = g_is64;
    int s = idx_at(ei, (size_t)e, is64);
    int d = idx_at(ei, (size_t)E + e, is64);
    int t = idx_at(et, (size_t)e, is64);
    float4 a = __ldg(&((const float4*)(z + (size_t)s * D))[lane]);
    float4 b = __ldg(&((const float4*)(z + (size_t)d * D))[lane]);
    float4 p = __ldg(&((const float4*)(phase + (size_t)t * D))[lane]);
    float r = a.x*cosf(p.x)*b.x + a.y*cosf(p.y)*b.y + a.z*cosf(p.z)*b.z + a.w*cosf(p.w)*b.w;
    #pragma unroll
    for (int o = 16; o; o >>= 1)
        r += __shfl_xor_sync(FULL, r, o);
    if (lane == 0)
        out[e] = r * __ldg(&g_inv[s]) * __ldg(&g_inv[d]);
}

// ---------------------------------------------------------------------------
// Launch. Inputs: z[f32 N*D], edge_index[2*E i32/i64], edge_type[E], phase_rel.
// ---------------------------------------------------------------------------
extern "C" void kernel_launch(void* const* d_in, const int* in_sizes, int n_in,
                              void* d_out, int out_size) {
    const float* z  = (const float*)d_in[0];
    const void*  ei = d_in[1];
    const void*  et = d_in[2];
    const float* ph = (const float*)d_in[3];
    float* out = (float*)d_out;

    int N  = in_sizes[0] / D;
    int E  = in_sizes[2];
    int RD = in_sizes[3];
    if (E <= 0) return;

    pre_kernel<<<(N + 7) / 8, 256>>>(z, N, ph, RD, (const unsigned int*)ei, E);

    int R = RD / D;
    if (R <= R_PAD) {
        int NB = (E + CH - 1) / CH;
        sedge_kernel<<<NB, TPB>>>(z, ei, et, out, E);
    } else {
        edge_fallback<<<(E + 7) / 8, 256>>>(z, ei, et, ph, out, E);
    }
}

// round 17
// speedup vs baseline: 1.4052x; 1.4040x over previous
#include <cuda_runtime.h>
#include <cuda_bf16.h>
#include <math.h>

// Problem constants (RotatEDecoder_30674656428511)
#define D       128
#define MAX_N   100000
#define MAX_R   500
#define FULL    0xffffffffu

// Scratch (allocation-free rule: static __device__ globals)
__device__ float g_inv[MAX_N];          // 1/max(||z_i||, eps) per node
__device__ float g_cosp[MAX_R * D];     // cos(phase_rel)
__device__ int   g_is64;                // 1 if index buffers are int64, 0 if int32

__device__ __forceinline__ int idx_at(const void* p, size_t i, int is64) {
    return is64 ? (int)__ldg(&((const long long*)p)[i])
                : __ldg(&((const int*)p)[i]);
}

// ---------------------------------------------------------------------------
// Fused pre-pass: dtype detect (warp-parallel ballot), cos table, per-node
// inverse norms. One launch.
// ---------------------------------------------------------------------------
__global__ __launch_bounds__(256)
void pre_kernel(const float* __restrict__ z, int N,
                const float* __restrict__ phase, int RD,
                const unsigned int* __restrict__ ei_words, int E) {
    if (blockIdx.x == 0 && threadIdx.x < 32) {
        int lane = threadIdx.x;
        unsigned int hi = (lane < E) ? ei_words[2 * lane + 1] : 0u;
        unsigned int any = __ballot_sync(FULL, hi != 0u);
        if (lane == 0) g_is64 = (any == 0u) ? 1 : 0;
    }

    int tid = blockIdx.x * blockDim.x + threadIdx.x;
    int nth = gridDim.x * blockDim.x;
    for (int i = tid; i < RD; i += nth)
        g_cosp[i] = cosf(phase[i]);

    int node = blockIdx.x * (blockDim.x >> 5) + (threadIdx.x >> 5);
    int lane = threadIdx.x & 31;
    if (node < N) {
        float4 v = reinterpret_cast<const float4*>(z + (size_t)node * D)[lane];
        float ss = v.x * v.x + v.y * v.y + v.z * v.z + v.w * v.w;
        #pragma unroll
        for (int o = 16; o; o >>= 1)
            ss += __shfl_xor_sync(FULL, ss, o);
        if (lane == 0)
            g_inv[node] = 1.0f / fmaxf(sqrtf(ss), 1e-12f);
    }
}

// ---------------------------------------------------------------------------
// Edge kernel: warp per FOUR edges.
//   out[e] = inv[s]*inv[d] * sum_k z[s][k] * cosp[t][k] * z[d][k]
// - Lane-gather index fetch: lanes 0-3 src, 4-7 dst, 8-11 type (one
//   predicated LDG) + shfl broadcast.
// - 12 independent LDG.128 gathers per warp.
// - Quarter-warp split reduction with ALL shfls executed convergently by the
//   full warp (selection only via arithmetic/selects, never divergent shfl).
// - Single float4 output store per warp.
// ---------------------------------------------------------------------------
__global__ __launch_bounds__(256)
void edge_kernel(const float* __restrict__ z,
                 const void* __restrict__ edge_index,
                 const void* __restrict__ edge_type,
                 float* __restrict__ out, int E) {
    int warp = blockIdx.x * (blockDim.x >> 5) + (threadIdx.x >> 5);
    int lane = threadIdx.x & 31;
    int base = warp * 4;
    if (base >= E) return;
    int is64 = g_is64;

    // --- lane-gather index fetch (lanes 0-11 active) ---
    int grp = lane >> 2;              // 0: src, 1: dst, 2: type
    int j   = lane & 3;
    int e_j = min(base + j, E - 1);
    int val = 0;
    if (grp < 3) {
        const void* p = (grp == 2) ? edge_type : edge_index;
        size_t off = (grp == 1) ? (size_t)E + e_j : (size_t)e_j;
        val = idx_at(p, off, is64);
    }
    int s[4], d[4], t[4];
    #pragma unroll
    for (int i = 0; i < 4; i++) {
        s[i] = __shfl_sync(FULL, val, i);
        d[i] = __shfl_sync(FULL, val, 4 + i);
        t[i] = __shfl_sync(FULL, val, 8 + i);
    }

    // --- inv gather: lanes 0-3 load inv[src_i], 4-7 load inv[dst_i] ---
    float iv = 0.0f;
    if (grp == 0)      iv = __ldg(&g_inv[s[j]]);
    else if (grp == 1) iv = __ldg(&g_inv[d[j]]);

    // --- 12 independent row gathers (issued before consumption) ---
    float4 A[4], B[4], C[4];
    #pragma unroll
    for (int i = 0; i < 4; i++) {
        A[i] = __ldg(&((const float4*)(z + (size_t)s[i] * D))[lane]);
        B[i] = __ldg(&((const float4*)(z + (size_t)d[i] * D))[lane]);
        C[i] = __ldg(&((const float4*)(g_cosp + t[i] * D))[lane]);
    }

    float r[4];
    #pragma unroll
    for (int i = 0; i < 4; i++)
        r[i] = A[i].x * C[i].x * B[i].x
             + A[i].y * C[i].y * B[i].y
             + A[i].z * C[i].z * B[i].z
             + A[i].w * C[i].w * B[i].w;

    // --- quarter-warp split reduction; every shfl convergent on all lanes ---
    float x0 = __shfl_xor_sync(FULL, r[0], 16);
    float x1 = __shfl_xor_sync(FULL, r[1], 16);
    float x2 = __shfl_xor_sync(FULL, r[2], 16);
    float x3 = __shfl_xor_sync(FULL, r[3], 16);
    float u = (lane < 16) ? (r[0] + x0) : (r[1] + x1);   // halves: e0 | e1
    float v = (lane < 16) ? (r[2] + x2) : (r[3] + x3);   // halves: e2 | e3

    float u8 = __shfl_xor_sync(FULL, u, 8);
    float v8 = __shfl_xor_sync(FULL, v, 8);
    float uu = u + u8;
    float vv = v + v8;
    float w = ((lane >> 3) & 1) ? vv : uu;   // 8-lane groups: e0, e2, e1, e3
    #pragma unroll
    for (int o = 4; o; o >>= 1)
        w += __shfl_xor_sync(FULL, w, o);

    // group -> edge map: {0,2,1,3}
    int g8 = lane >> 3;
    int eidx = (g8 == 0) ? 0 : (g8 == 1) ? 2 : (g8 == 2) ? 1 : 3;
    float iv_s = __shfl_sync(FULL, iv, eidx);
    float iv_d = __shfl_sync(FULL, iv, 4 + eidx);
    float scaled = w * iv_s * iv_d;           // each group holds its edge's result

    // gather e0..e3 to lane 0 (from lanes 0, 16, 8, 24) and store float4
    float o1v = __shfl_sync(FULL, scaled, 16);
    float o2v = __shfl_sync(FULL, scaled, 8);
    float o3v = __shfl_sync(FULL, scaled, 24);
    if (lane == 0) {
        if (base + 3 < E) {
            *reinterpret_cast<float4*>(out + base) = make_float4(scaled, o1v, o2v, o3v);
        } else {
            out[base] = scaled;
            if (base + 1 < E) out[base + 1] = o1v;
            if (base + 2 < E) out[base + 2] = o2v;
            if (base + 3 < E) out[base + 3] = o3v;
        }
    }
}

// ---------------------------------------------------------------------------
// Launch. Inputs (metadata order): z[f32 N*D], edge_index[2*E int32 or int64],
// edge_type[E same dtype], phase_rel[f32 R*D]. Output: f32 [E].
// ---------------------------------------------------------------------------
extern "C" void kernel_launch(void* const* d_in, const int* in_sizes, int n_in,
                              void* d_out, int out_size) {
    const float* z  = (const float*)d_in[0];
    const void*  ei = d_in[1];
    const void*  et = d_in[2];
    const float* ph = (const float*)d_in[3];
    float* out = (float*)d_out;

    int N  = in_sizes[0] / D;
    int E  = in_sizes[2];
    int RD = in_sizes[3];
    if (E <= 0) return;

    pre_kernel<<<(N + 7) / 8, 256>>>(z, N, ph, RD, (const unsigned int*)ei, E);
    // 8 warps/block, 4 edges/warp -> 32 edges/block
    int warps = (E + 3) / 4;
    edge_kernel<<<(warps + 7) / 8, 256>>>(z, ei, et, out, E);
}